// round 7
// baseline (speedup 1.0000x reference)
#include <cuda_runtime.h>
#include <cuda_fp16.h>
#include <cstdint>
#include <cstddef>

// Problem constants
#define Bn   8
#define Qn   900
#define En   256
#define NHn  8
#define HDn  32
#define NLn  4
#define NPn  4
#define Sn   19560
#define BQn  (Bn * Qn)          // 7200
#define Mv   (Bn * Sn)          // 156480

// Scratch (static device globals)
__device__ __half g_vh[(size_t)Bn * Sn * En];    // projected values [B,S,E] fp16
__device__ float g_off[(size_t)BQn * 256];
__device__ float g_logits[(size_t)BQn * 128];
__device__ float g_mid[(size_t)BQn * En];

// ---------------------------------------------------------------------------
// fp16 tensor-core GEMM (m16n8k16) for the value projection.
// C_half[M,N] = A_f32[M,K] @ B_f32[K,N] + bias.  CTA 128x128, K-chunk 32,
// 8 warps (2m x 4n), warp tile 64x32.
// ---------------------------------------------------------------------------
__device__ __forceinline__ void mma_f16(float* c, const uint32_t* a, const uint32_t* b) {
    asm volatile(
        "mma.sync.aligned.m16n8k16.row.col.f32.f16.f16.f32 "
        "{%0,%1,%2,%3}, {%4,%5,%6,%7}, {%8,%9}, {%0,%1,%2,%3};"
        : "+f"(c[0]), "+f"(c[1]), "+f"(c[2]), "+f"(c[3])
        : "r"(a[0]), "r"(a[1]), "r"(a[2]), "r"(a[3]), "r"(b[0]), "r"(b[1]));
}

__global__ __launch_bounds__(256, 2)
void gemm_f16v(const float* __restrict__ A, const float* __restrict__ Bw,
               const float* __restrict__ bias, __half* __restrict__ C,
               int M, int N, int K)
{
    __shared__ __half As[128][40];    // [m][k 0..31], pad 40 halves (80 B rows)
    __shared__ __half Bsn[128][40];   // [n][k 0..31] (transposed at load)

    const int tid  = threadIdx.x;
    const int lane = tid & 31;
    const int wid  = tid >> 5;
    const int wm   = wid >> 2;
    const int wn   = wid & 3;
    const int g    = lane >> 2;
    const int tg   = lane & 3;
    const int m0   = blockIdx.y * 128;
    const int n0   = blockIdx.x * 128;

    float c[4][4][4];
#pragma unroll
    for (int i = 0; i < 4; i++)
#pragma unroll
        for (int j = 0; j < 4; j++)
#pragma unroll
            for (int r = 0; r < 4; r++) c[i][j][r] = 0.0f;

    const int a_kq = tid & 7;          // float4 col within K-chunk
    const int a_m  = tid >> 3;         // 0..31
    const int b_n4 = tid & 31;         // float4 col within N tile
    const int b_k  = tid >> 5;         // 0..7

    for (int k0 = 0; k0 < K; k0 += 32) {
        // A tile 128x32 -> half
#pragma unroll
        for (int i = 0; i < 4; i++) {
            int m = a_m + 32 * i;
            float4 v = make_float4(0.f, 0.f, 0.f, 0.f);
            if (m0 + m < M) v = *(const float4*)(A + (size_t)(m0 + m) * K + k0 + a_kq * 4);
            __half2 h01 = __floats2half2_rn(v.x, v.y);
            __half2 h23 = __floats2half2_rn(v.z, v.w);
            uint2 pk;
            pk.x = *(uint32_t*)&h01;
            pk.y = *(uint32_t*)&h23;
            *(uint2*)&As[m][a_kq * 4] = pk;
        }
        // B tile 32x128 -> half, transposed into Bsn[n][k]
#pragma unroll
        for (int i = 0; i < 4; i++) {
            int k = b_k + 8 * i;
            float4 v = *(const float4*)(Bw + (size_t)(k0 + k) * N + n0 + b_n4 * 4);
            Bsn[b_n4 * 4 + 0][k] = __float2half_rn(v.x);
            Bsn[b_n4 * 4 + 1][k] = __float2half_rn(v.y);
            Bsn[b_n4 * 4 + 2][k] = __float2half_rn(v.z);
            Bsn[b_n4 * 4 + 3][k] = __float2half_rn(v.w);
        }
        __syncthreads();

#pragma unroll
        for (int kk = 0; kk < 2; kk++) {
            uint32_t a[4][4], b[4][2];
#pragma unroll
            for (int mf = 0; mf < 4; mf++) {
                int m = wm * 64 + mf * 16 + g;
                a[mf][0] = *(const uint32_t*)&As[m][kk * 16 + 2 * tg];
                a[mf][1] = *(const uint32_t*)&As[m + 8][kk * 16 + 2 * tg];
                a[mf][2] = *(const uint32_t*)&As[m][kk * 16 + 2 * tg + 8];
                a[mf][3] = *(const uint32_t*)&As[m + 8][kk * 16 + 2 * tg + 8];
            }
#pragma unroll
            for (int nf = 0; nf < 4; nf++) {
                int n = wn * 32 + nf * 8 + g;
                b[nf][0] = *(const uint32_t*)&Bsn[n][kk * 16 + 2 * tg];
                b[nf][1] = *(const uint32_t*)&Bsn[n][kk * 16 + 2 * tg + 8];
            }
#pragma unroll
            for (int mf = 0; mf < 4; mf++)
#pragma unroll
                for (int nf = 0; nf < 4; nf++)
                    mma_f16(c[mf][nf], a[mf], b[nf]);
        }
        __syncthreads();
    }

    // Epilogue: +bias, convert to half, 4-byte stores
#pragma unroll
    for (int mf = 0; mf < 4; mf++) {
        const int r0 = m0 + wm * 64 + mf * 16 + g;
        const int r1 = r0 + 8;
#pragma unroll
        for (int nf = 0; nf < 4; nf++) {
            const int cb = n0 + wn * 32 + nf * 8 + 2 * tg;
            const float bx = bias[cb], by = bias[cb + 1];
            if (r0 < M) {
                __half2 o = __floats2half2_rn(c[mf][nf][0] + bx, c[mf][nf][1] + by);
                *(__half2*)(C + (size_t)r0 * N + cb) = o;
            }
            if (r1 < M) {
                __half2 o = __floats2half2_rn(c[mf][nf][2] + bx, c[mf][nf][3] + by);
                *(__half2*)(C + (size_t)r1 * N + cb) = o;
            }
        }
    }
}

// ---------------------------------------------------------------------------
// tf32 tensor-core GEMM — round-6 proven (steps 2,3,5). Unchanged.
// ---------------------------------------------------------------------------
__device__ __forceinline__ uint32_t f2tf32(float f) {
    uint32_t r;
    asm("cvt.rna.tf32.f32 %0, %1;" : "=r"(r) : "f"(f));
    return r;
}

__device__ __forceinline__ void mma_tf32(float* c, const uint32_t* a, const uint32_t* b) {
    asm volatile(
        "mma.sync.aligned.m16n8k8.row.col.f32.tf32.tf32.f32 "
        "{%0,%1,%2,%3}, {%4,%5,%6,%7}, {%8,%9}, {%0,%1,%2,%3};"
        : "+f"(c[0]), "+f"(c[1]), "+f"(c[2]), "+f"(c[3])
        : "r"(a[0]), "r"(a[1]), "r"(a[2]), "r"(a[3]), "r"(b[0]), "r"(b[1]));
}

__global__ __launch_bounds__(256, 2)
void gemm_tf32(const float* __restrict__ A, const float* __restrict__ Bw,
               const float* __restrict__ bias, const float* __restrict__ resid,
               float* __restrict__ C, int M, int N, int K)
{
    __shared__ uint32_t As[128][36];
    __shared__ uint32_t Bs[32][132];

    const int tid  = threadIdx.x;
    const int lane = tid & 31;
    const int wid  = tid >> 5;
    const int wm   = wid >> 2;
    const int wn   = wid & 3;
    const int g    = lane >> 2;
    const int tg   = lane & 3;
    const int m0   = blockIdx.y * 128;
    const int n0   = blockIdx.x * 128;

    float c[4][4][4];
#pragma unroll
    for (int i = 0; i < 4; i++)
#pragma unroll
        for (int j = 0; j < 4; j++)
#pragma unroll
            for (int r = 0; r < 4; r++) c[i][j][r] = 0.0f;

    const int a_kq = tid & 7;
    const int a_m  = tid >> 3;
    const int b_n4 = tid & 31;
    const int b_k  = tid >> 5;

    for (int k0 = 0; k0 < K; k0 += 32) {
#pragma unroll
        for (int i = 0; i < 4; i++) {
            int m = a_m + 32 * i;
            float4 v = make_float4(0.f, 0.f, 0.f, 0.f);
            if (m0 + m < M) v = *(const float4*)(A + (size_t)(m0 + m) * K + k0 + a_kq * 4);
            uint4 t;
            t.x = f2tf32(v.x); t.y = f2tf32(v.y); t.z = f2tf32(v.z); t.w = f2tf32(v.w);
            *(uint4*)&As[m][a_kq * 4] = t;
        }
#pragma unroll
        for (int i = 0; i < 4; i++) {
            int k = b_k + 8 * i;
            float4 v = *(const float4*)(Bw + (size_t)(k0 + k) * N + n0 + b_n4 * 4);
            uint4 t;
            t.x = f2tf32(v.x); t.y = f2tf32(v.y); t.z = f2tf32(v.z); t.w = f2tf32(v.w);
            *(uint4*)&Bs[k][b_n4 * 4] = t;
        }
        __syncthreads();

#pragma unroll
        for (int kk = 0; kk < 4; kk++) {
            uint32_t a[4][4], b[4][2];
#pragma unroll
            for (int mf = 0; mf < 4; mf++) {
                int m = wm * 64 + mf * 16 + g;
                a[mf][0] = As[m][kk * 8 + tg];
                a[mf][1] = As[m + 8][kk * 8 + tg];
                a[mf][2] = As[m][kk * 8 + tg + 4];
                a[mf][3] = As[m + 8][kk * 8 + tg + 4];
            }
#pragma unroll
            for (int nf = 0; nf < 4; nf++) {
                int n = wn * 32 + nf * 8 + g;
                b[nf][0] = Bs[kk * 8 + tg][n];
                b[nf][1] = Bs[kk * 8 + tg + 4][n];
            }
#pragma unroll
            for (int mf = 0; mf < 4; mf++)
#pragma unroll
                for (int nf = 0; nf < 4; nf++)
                    mma_tf32(c[mf][nf], a[mf], b[nf]);
        }
        __syncthreads();
    }

#pragma unroll
    for (int mf = 0; mf < 4; mf++) {
        const int r0 = m0 + wm * 64 + mf * 16 + g;
        const int r1 = r0 + 8;
#pragma unroll
        for (int nf = 0; nf < 4; nf++) {
            const int cb = n0 + wn * 32 + nf * 8 + 2 * tg;
            const float bx = bias[cb], by = bias[cb + 1];
            if (r0 < M) {
                float2 o = make_float2(c[mf][nf][0] + bx, c[mf][nf][1] + by);
                if (resid) {
                    const float2 rr = *(const float2*)(resid + (size_t)r0 * N + cb);
                    o.x += rr.x; o.y += rr.y;
                }
                *(float2*)(C + (size_t)r0 * N + cb) = o;
            }
            if (r1 < M) {
                float2 o = make_float2(c[mf][nf][2] + bx, c[mf][nf][3] + by);
                if (resid) {
                    const float2 rr = *(const float2*)(resid + (size_t)r1 * N + cb);
                    o.x += rr.x; o.y += rr.y;
                }
                *(float2*)(C + (size_t)r1 * N + cb) = o;
            }
        }
    }
}

// ---------------------------------------------------------------------------
// Fused softmax + deformable sampling — round-5 proven structure; v is fp16.
// ---------------------------------------------------------------------------
__global__ __launch_bounds__(256, 4)
void msda_sample(const float* __restrict__ off, const float* __restrict__ logits,
                 const float* __restrict__ ref, const __half* __restrict__ v,
                 float* __restrict__ mid)
{
    const int lvlH[NLn]     = {92, 46, 23, 12};
    const int lvlW[NLn]     = {160, 80, 40, 20};
    const int lvlStart[NLn] = {0, 14720, 18400, 19320};

    const int row = blockIdx.x;
    const int b   = row / Qn;
    const int t   = threadIdx.x;

    __shared__ float s_loc[256];
    __shared__ float s_lg[128];
    __shared__ int4   s_idx[128];
    __shared__ float4 s_wgt[128];

    {
        const int c = t & 1;
        const int l = (t >> 3) & 3;
        const float dim = (c == 0) ? (float)lvlW[l] : (float)lvlH[l];
        const float r = ref[((size_t)row * NLn + l) * 2 + c];
        s_loc[t] = r * dim - 0.5f + off[(size_t)row * 256 + t];
    }
    if (t < 128) s_lg[t] = logits[(size_t)row * 128 + t];
    __syncthreads();

    if (t < 128) {
        const int h = t >> 4;
        float m = -1e30f;
#pragma unroll
        for (int i = 0; i < 16; i++) m = fmaxf(m, s_lg[h * 16 + i]);
        float sum = 0.0f;
#pragma unroll
        for (int i = 0; i < 16; i++) sum += __expf(s_lg[h * 16 + i] - m);
        const float w = __expf(s_lg[t] - m) / sum;

        const int l = (t >> 2) & 3;
        const int Hl = lvlH[l], Wl = lvlW[l], base = lvlStart[l];
        const float x = s_loc[t * 2 + 0];
        const float y = s_loc[t * 2 + 1];
        const float xf = floorf(x), yf = floorf(y);
        const float wx = x - xf, wy = y - yf;
        const int x0 = (int)xf, y0 = (int)yf, x1 = x0 + 1, y1 = y0 + 1;

        const bool vx0 = (x0 >= 0) & (x0 < Wl), vx1 = (x1 >= 0) & (x1 < Wl);
        const bool vy0 = (y0 >= 0) & (y0 < Hl), vy1 = (y1 >= 0) & (y1 < Hl);
        const int xc0 = min(max(x0, 0), Wl - 1), xc1 = min(max(x1, 0), Wl - 1);
        const int yc0 = min(max(y0, 0), Hl - 1), yc1 = min(max(y1, 0), Hl - 1);

        int4 id;
        id.x = base + yc0 * Wl + xc0;
        id.y = base + yc0 * Wl + xc1;
        id.z = base + yc1 * Wl + xc0;
        id.w = base + yc1 * Wl + xc1;
        s_idx[t] = id;
        float4 ww;
        ww.x = (vy0 & vx0) ? w * (1.f - wy) * (1.f - wx) : 0.f;
        ww.y = (vy0 & vx1) ? w * (1.f - wy) * wx : 0.f;
        ww.z = (vy1 & vx0) ? w * wy * (1.f - wx) : 0.f;
        ww.w = (vy1 & vx1) ? w * wy * wx : 0.f;
        s_wgt[t] = ww;
    }
    __syncthreads();

    const int h = t >> 5;
    const int d = t & 31;
    const __half* __restrict__ vb = v + (size_t)b * Sn * En + h * HDn + d;

    float acc = 0.0f;
#pragma unroll
    for (int s = 0; s < 16; s++) {
        const int si = h * 16 + s;
        const int4   id = s_idx[si];
        const float4 ww = s_wgt[si];
        acc += ww.x * __half2float(vb[(size_t)id.x * En]);
        acc += ww.y * __half2float(vb[(size_t)id.y * En]);
        acc += ww.z * __half2float(vb[(size_t)id.z * En]);
        acc += ww.w * __half2float(vb[(size_t)id.w * En]);
    }

    mid[(size_t)row * En + t] = acc;
}

// ---------------------------------------------------------------------------
extern "C" void kernel_launch(void* const* d_in, const int* in_sizes, int n_in,
                              void* d_out, int out_size)
{
    const float* query  = (const float*)d_in[0];
    const float* value  = (const float*)d_in[1];
    const float* refpts = (const float*)d_in[2];
    const float* W_off  = (const float*)d_in[4];
    const float* b_off  = (const float*)d_in[5];
    const float* W_attn = (const float*)d_in[6];
    const float* b_attn = (const float*)d_in[7];
    const float* W_v    = (const float*)d_in[8];
    const float* b_v    = (const float*)d_in[9];
    const float* W_out  = (const float*)d_in[10];
    const float* b_out  = (const float*)d_in[11];
    float* out = (float*)d_out;

    void *pvh, *poff, *plg, *pmid;
    cudaGetSymbolAddress(&pvh, g_vh);
    cudaGetSymbolAddress(&poff, g_off);
    cudaGetSymbolAddress(&plg, g_logits);
    cudaGetSymbolAddress(&pmid, g_mid);
    __half* vh_s = (__half*)pvh;
    float* off_s = (float*)poff;
    float* lg_s  = (float*)plg;
    float* mid_s = (float*)pmid;

    // 1) value projection: [156480,256] @ [256,256]  (fp16 MMA, half output)
    {
        dim3 grid(En / 128, (Mv + 127) / 128);
        gemm_f16v<<<grid, 256>>>(value, W_v, b_v, vh_s, Mv, En, En);
    }
    // 2) sampling-offset projection: [7200,256] @ [256,256]  (tf32)
    {
        dim3 grid(256 / 128, (BQn + 127) / 128);
        gemm_tf32<<<grid, 256>>>(query, W_off, b_off, nullptr, off_s, BQn, 256, En);
    }
    // 3) attention-logit projection: [7200,256] @ [256,128]  (tf32)
    {
        dim3 grid(128 / 128, (BQn + 127) / 128);
        gemm_tf32<<<grid, 256>>>(query, W_attn, b_attn, nullptr, lg_s, BQn, 128, En);
    }
    // 4) softmax + deformable bilinear sampling (fp16 gathers)
    msda_sample<<<BQn, 256>>>(off_s, lg_s, refpts, vh_s, mid_s);
    // 5) output projection + residual: [7200,256] @ [256,256] + query  (tf32)
    {
        dim3 grid(En / 128, (BQn + 127) / 128);
        gemm_tf32<<<grid, 256>>>(mid_s, W_out, b_out, query, out, BQn, En, En);
    }
}

// round 8
// speedup vs baseline: 1.5989x; 1.5989x over previous
#include <cuda_runtime.h>
#include <cuda_fp16.h>
#include <cstdint>
#include <cstddef>

// Problem constants
#define Bn   8
#define Qn   900
#define En   256
#define NHn  8
#define HDn  32
#define NLn  4
#define NPn  4
#define Sn   19560
#define BQn  (Bn * Qn)          // 7200
#define Mv   (Bn * Sn)          // 156480

// Scratch (static device globals)
__device__ __half g_vh[(size_t)Bn * Sn * En];    // projected values [B,S,E] fp16
__device__ __half g_wt[(size_t)En * En];         // W_v^T fp16  [n][k]
__device__ float g_off[(size_t)BQn * 256];
__device__ float g_logits[(size_t)BQn * 128];
__device__ float g_mid[(size_t)BQn * En];

// ---------------------------------------------------------------------------
// W_v transpose + fp16 convert: Wt[n][k] = half(W[k][n]), 256x256.
// ---------------------------------------------------------------------------
__global__ void transpose_w_h(const float* __restrict__ W, __half* __restrict__ Wt)
{
    __shared__ float tile[32][33];
    const int bx = blockIdx.x * 32;   // n block
    const int by = blockIdx.y * 32;   // k block
    const int tx = threadIdx.x, ty = threadIdx.y;   // 32 x 8
#pragma unroll
    for (int i = 0; i < 32; i += 8)
        tile[ty + i][tx] = W[(size_t)(by + ty + i) * En + bx + tx];
    __syncthreads();
#pragma unroll
    for (int i = 0; i < 32; i += 8)
        Wt[(size_t)(bx + ty + i) * En + by + tx] = __float2half_rn(tile[tx][ty + i]);
}

// ---------------------------------------------------------------------------
// fp16 tensor-core GEMM (m16n8k16) for the value projection.
// C_half[M,N] = A_f32[M,K] @ Wt_h^T + bias  (Wt is [n][k] fp16).
// CTA 128x128, K-chunk 32, 8 warps (2m x 4n), warp tile 64x32.
// Fragment-load layouts identical to round 7 (proven correct & conflict-free).
// ---------------------------------------------------------------------------
__device__ __forceinline__ void mma_f16(float* c, const uint32_t* a, const uint32_t* b) {
    asm volatile(
        "mma.sync.aligned.m16n8k16.row.col.f32.f16.f16.f32 "
        "{%0,%1,%2,%3}, {%4,%5,%6,%7}, {%8,%9}, {%0,%1,%2,%3};"
        : "+f"(c[0]), "+f"(c[1]), "+f"(c[2]), "+f"(c[3])
        : "r"(a[0]), "r"(a[1]), "r"(a[2]), "r"(a[3]), "r"(b[0]), "r"(b[1]));
}

__global__ __launch_bounds__(256, 2)
void gemm_f16v(const float* __restrict__ A, const __half* __restrict__ Wt,
               const float* __restrict__ bias, __half* __restrict__ C,
               int M, int N, int K)
{
    __shared__ __half As[128][40];    // [m][k 0..31], 80 B rows
    __shared__ __half Bsn[128][40];   // [n][k 0..31], 80 B rows

    const int tid  = threadIdx.x;
    const int lane = tid & 31;
    const int wid  = tid >> 5;
    const int wm   = wid >> 2;
    const int wn   = wid & 3;
    const int g    = lane >> 2;
    const int tg   = lane & 3;
    const int m0   = blockIdx.y * 128;
    const int n0   = blockIdx.x * 128;

    float c[4][4][4];
#pragma unroll
    for (int i = 0; i < 4; i++)
#pragma unroll
        for (int j = 0; j < 4; j++)
#pragma unroll
            for (int r = 0; r < 4; r++) c[i][j][r] = 0.0f;

    const int a_kq = tid & 7;          // float4 col within K-chunk
    const int a_m  = tid >> 3;         // 0..31
    const int b_nr = tid >> 2;         // 0..63 (B row within tile half)
    const int b_q  = tid & 3;          // uint4 (8 halves) index within 32-k row

    for (int k0 = 0; k0 < K; k0 += 32) {
        // A tile 128x32 fp32 -> half (coalesced)
#pragma unroll
        for (int i = 0; i < 4; i++) {
            int m = a_m + 32 * i;
            float4 v = make_float4(0.f, 0.f, 0.f, 0.f);
            if (m0 + m < M) v = *(const float4*)(A + (size_t)(m0 + m) * K + k0 + a_kq * 4);
            __half2 h01 = __floats2half2_rn(v.x, v.y);
            __half2 h23 = __floats2half2_rn(v.z, v.w);
            uint2 pk;
            pk.x = *(uint32_t*)&h01;
            pk.y = *(uint32_t*)&h23;
            *(uint2*)&As[m][a_kq * 4] = pk;
        }
        // B tile: direct copy from pre-transposed fp16 Wt[n][k] (no transpose here)
#pragma unroll
        for (int i = 0; i < 2; i++) {
            int n = b_nr + 64 * i;
            uint4 v = *(const uint4*)(Wt + (size_t)(n0 + n) * K + k0 + b_q * 8);
            *(uint4*)&Bsn[n][b_q * 8] = v;
        }
        __syncthreads();

#pragma unroll
        for (int kk = 0; kk < 2; kk++) {
            uint32_t a[4][4], b[4][2];
#pragma unroll
            for (int mf = 0; mf < 4; mf++) {
                int m = wm * 64 + mf * 16 + g;
                a[mf][0] = *(const uint32_t*)&As[m][kk * 16 + 2 * tg];
                a[mf][1] = *(const uint32_t*)&As[m + 8][kk * 16 + 2 * tg];
                a[mf][2] = *(const uint32_t*)&As[m][kk * 16 + 2 * tg + 8];
                a[mf][3] = *(const uint32_t*)&As[m + 8][kk * 16 + 2 * tg + 8];
            }
#pragma unroll
            for (int nf = 0; nf < 4; nf++) {
                int n = wn * 32 + nf * 8 + g;
                b[nf][0] = *(const uint32_t*)&Bsn[n][kk * 16 + 2 * tg];
                b[nf][1] = *(const uint32_t*)&Bsn[n][kk * 16 + 2 * tg + 8];
            }
#pragma unroll
            for (int mf = 0; mf < 4; mf++)
#pragma unroll
                for (int nf = 0; nf < 4; nf++)
                    mma_f16(c[mf][nf], a[mf], b[nf]);
        }
        __syncthreads();
    }

    // Epilogue: +bias, convert to half, 4-byte stores
#pragma unroll
    for (int mf = 0; mf < 4; mf++) {
        const int r0 = m0 + wm * 64 + mf * 16 + g;
        const int r1 = r0 + 8;
#pragma unroll
        for (int nf = 0; nf < 4; nf++) {
            const int cb = n0 + wn * 32 + nf * 8 + 2 * tg;
            const float bx = bias[cb], by = bias[cb + 1];
            if (r0 < M) {
                __half2 o = __floats2half2_rn(c[mf][nf][0] + bx, c[mf][nf][1] + by);
                *(__half2*)(C + (size_t)r0 * N + cb) = o;
            }
            if (r1 < M) {
                __half2 o = __floats2half2_rn(c[mf][nf][2] + bx, c[mf][nf][3] + by);
                *(__half2*)(C + (size_t)r1 * N + cb) = o;
            }
        }
    }
}

// ---------------------------------------------------------------------------
// tf32 tensor-core GEMM — proven (steps 2,3,5). Unchanged.
// ---------------------------------------------------------------------------
__device__ __forceinline__ uint32_t f2tf32(float f) {
    uint32_t r;
    asm("cvt.rna.tf32.f32 %0, %1;" : "=r"(r) : "f"(f));
    return r;
}

__device__ __forceinline__ void mma_tf32(float* c, const uint32_t* a, const uint32_t* b) {
    asm volatile(
        "mma.sync.aligned.m16n8k8.row.col.f32.tf32.tf32.f32 "
        "{%0,%1,%2,%3}, {%4,%5,%6,%7}, {%8,%9}, {%0,%1,%2,%3};"
        : "+f"(c[0]), "+f"(c[1]), "+f"(c[2]), "+f"(c[3])
        : "r"(a[0]), "r"(a[1]), "r"(a[2]), "r"(a[3]), "r"(b[0]), "r"(b[1]));
}

__global__ __launch_bounds__(256, 2)
void gemm_tf32(const float* __restrict__ A, const float* __restrict__ Bw,
               const float* __restrict__ bias, const float* __restrict__ resid,
               float* __restrict__ C, int M, int N, int K)
{
    __shared__ uint32_t As[128][36];
    __shared__ uint32_t Bs[32][132];

    const int tid  = threadIdx.x;
    const int lane = tid & 31;
    const int wid  = tid >> 5;
    const int wm   = wid >> 2;
    const int wn   = wid & 3;
    const int g    = lane >> 2;
    const int tg   = lane & 3;
    const int m0   = blockIdx.y * 128;
    const int n0   = blockIdx.x * 128;

    float c[4][4][4];
#pragma unroll
    for (int i = 0; i < 4; i++)
#pragma unroll
        for (int j = 0; j < 4; j++)
#pragma unroll
            for (int r = 0; r < 4; r++) c[i][j][r] = 0.0f;

    const int a_kq = tid & 7;
    const int a_m  = tid >> 3;
    const int b_n4 = tid & 31;
    const int b_k  = tid >> 5;

    for (int k0 = 0; k0 < K; k0 += 32) {
#pragma unroll
        for (int i = 0; i < 4; i++) {
            int m = a_m + 32 * i;
            float4 v = make_float4(0.f, 0.f, 0.f, 0.f);
            if (m0 + m < M) v = *(const float4*)(A + (size_t)(m0 + m) * K + k0 + a_kq * 4);
            uint4 t;
            t.x = f2tf32(v.x); t.y = f2tf32(v.y); t.z = f2tf32(v.z); t.w = f2tf32(v.w);
            *(uint4*)&As[m][a_kq * 4] = t;
        }
#pragma unroll
        for (int i = 0; i < 4; i++) {
            int k = b_k + 8 * i;
            float4 v = *(const float4*)(Bw + (size_t)(k0 + k) * N + n0 + b_n4 * 4);
            uint4 t;
            t.x = f2tf32(v.x); t.y = f2tf32(v.y); t.z = f2tf32(v.z); t.w = f2tf32(v.w);
            *(uint4*)&Bs[k][b_n4 * 4] = t;
        }
        __syncthreads();

#pragma unroll
        for (int kk = 0; kk < 4; kk++) {
            uint32_t a[4][4], b[4][2];
#pragma unroll
            for (int mf = 0; mf < 4; mf++) {
                int m = wm * 64 + mf * 16 + g;
                a[mf][0] = As[m][kk * 8 + tg];
                a[mf][1] = As[m + 8][kk * 8 + tg];
                a[mf][2] = As[m][kk * 8 + tg + 4];
                a[mf][3] = As[m + 8][kk * 8 + tg + 4];
            }
#pragma unroll
            for (int nf = 0; nf < 4; nf++) {
                int n = wn * 32 + nf * 8 + g;
                b[nf][0] = Bs[kk * 8 + tg][n];
                b[nf][1] = Bs[kk * 8 + tg + 4][n];
            }
#pragma unroll
            for (int mf = 0; mf < 4; mf++)
#pragma unroll
                for (int nf = 0; nf < 4; nf++)
                    mma_tf32(c[mf][nf], a[mf], b[nf]);
        }
        __syncthreads();
    }

#pragma unroll
    for (int mf = 0; mf < 4; mf++) {
        const int r0 = m0 + wm * 64 + mf * 16 + g;
        const int r1 = r0 + 8;
#pragma unroll
        for (int nf = 0; nf < 4; nf++) {
            const int cb = n0 + wn * 32 + nf * 8 + 2 * tg;
            const float bx = bias[cb], by = bias[cb + 1];
            if (r0 < M) {
                float2 o = make_float2(c[mf][nf][0] + bx, c[mf][nf][1] + by);
                if (resid) {
                    const float2 rr = *(const float2*)(resid + (size_t)r0 * N + cb);
                    o.x += rr.x; o.y += rr.y;
                }
                *(float2*)(C + (size_t)r0 * N + cb) = o;
            }
            if (r1 < M) {
                float2 o = make_float2(c[mf][nf][2] + bx, c[mf][nf][3] + by);
                if (resid) {
                    const float2 rr = *(const float2*)(resid + (size_t)r1 * N + cb);
                    o.x += rr.x; o.y += rr.y;
                }
                *(float2*)(C + (size_t)r1 * N + cb) = o;
            }
        }
    }
}

// ---------------------------------------------------------------------------
// Fused softmax + deformable sampling — proven structure; v is fp16.
// ---------------------------------------------------------------------------
__global__ __launch_bounds__(256, 4)
void msda_sample(const float* __restrict__ off, const float* __restrict__ logits,
                 const float* __restrict__ ref, const __half* __restrict__ v,
                 float* __restrict__ mid)
{
    const int lvlH[NLn]     = {92, 46, 23, 12};
    const int lvlW[NLn]     = {160, 80, 40, 20};
    const int lvlStart[NLn] = {0, 14720, 18400, 19320};

    const int row = blockIdx.x;
    const int b   = row / Qn;
    const int t   = threadIdx.x;

    __shared__ float s_loc[256];
    __shared__ float s_lg[128];
    __shared__ int4   s_idx[128];
    __shared__ float4 s_wgt[128];

    {
        const int c = t & 1;
        const int l = (t >> 3) & 3;
        const float dim = (c == 0) ? (float)lvlW[l] : (float)lvlH[l];
        const float r = ref[((size_t)row * NLn + l) * 2 + c];
        s_loc[t] = r * dim - 0.5f + off[(size_t)row * 256 + t];
    }
    if (t < 128) s_lg[t] = logits[(size_t)row * 128 + t];
    __syncthreads();

    if (t < 128) {
        const int h = t >> 4;
        float m = -1e30f;
#pragma unroll
        for (int i = 0; i < 16; i++) m = fmaxf(m, s_lg[h * 16 + i]);
        float sum = 0.0f;
#pragma unroll
        for (int i = 0; i < 16; i++) sum += __expf(s_lg[h * 16 + i] - m);
        const float w = __expf(s_lg[t] - m) / sum;

        const int l = (t >> 2) & 3;
        const int Hl = lvlH[l], Wl = lvlW[l], base = lvlStart[l];
        const float x = s_loc[t * 2 + 0];
        const float y = s_loc[t * 2 + 1];
        const float xf = floorf(x), yf = floorf(y);
        const float wx = x - xf, wy = y - yf;
        const int x0 = (int)xf, y0 = (int)yf, x1 = x0 + 1, y1 = y0 + 1;

        const bool vx0 = (x0 >= 0) & (x0 < Wl), vx1 = (x1 >= 0) & (x1 < Wl);
        const bool vy0 = (y0 >= 0) & (y0 < Hl), vy1 = (y1 >= 0) & (y1 < Hl);
        const int xc0 = min(max(x0, 0), Wl - 1), xc1 = min(max(x1, 0), Wl - 1);
        const int yc0 = min(max(y0, 0), Hl - 1), yc1 = min(max(y1, 0), Hl - 1);

        int4 id;
        id.x = base + yc0 * Wl + xc0;
        id.y = base + yc0 * Wl + xc1;
        id.z = base + yc1 * Wl + xc0;
        id.w = base + yc1 * Wl + xc1;
        s_idx[t] = id;
        float4 ww;
        ww.x = (vy0 & vx0) ? w * (1.f - wy) * (1.f - wx) : 0.f;
        ww.y = (vy0 & vx1) ? w * (1.f - wy) * wx : 0.f;
        ww.z = (vy1 & vx0) ? w * wy * (1.f - wx) : 0.f;
        ww.w = (vy1 & vx1) ? w * wy * wx : 0.f;
        s_wgt[t] = ww;
    }
    __syncthreads();

    const int h = t >> 5;
    const int d = t & 31;
    const __half* __restrict__ vb = v + (size_t)b * Sn * En + h * HDn + d;

    float acc = 0.0f;
#pragma unroll
    for (int s = 0; s < 16; s++) {
        const int si = h * 16 + s;
        const int4   id = s_idx[si];
        const float4 ww = s_wgt[si];
        acc += ww.x * __half2float(vb[(size_t)id.x * En]);
        acc += ww.y * __half2float(vb[(size_t)id.y * En]);
        acc += ww.z * __half2float(vb[(size_t)id.z * En]);
        acc += ww.w * __half2float(vb[(size_t)id.w * En]);
    }

    mid[(size_t)row * En + t] = acc;
}

// ---------------------------------------------------------------------------
extern "C" void kernel_launch(void* const* d_in, const int* in_sizes, int n_in,
                              void* d_out, int out_size)
{
    const float* query  = (const float*)d_in[0];
    const float* value  = (const float*)d_in[1];
    const float* refpts = (const float*)d_in[2];
    const float* W_off  = (const float*)d_in[4];
    const float* b_off  = (const float*)d_in[5];
    const float* W_attn = (const float*)d_in[6];
    const float* b_attn = (const float*)d_in[7];
    const float* W_v    = (const float*)d_in[8];
    const float* b_v    = (const float*)d_in[9];
    const float* W_out  = (const float*)d_in[10];
    const float* b_out  = (const float*)d_in[11];
    float* out = (float*)d_out;

    void *pvh, *pwt, *poff, *plg, *pmid;
    cudaGetSymbolAddress(&pvh, g_vh);
    cudaGetSymbolAddress(&pwt, g_wt);
    cudaGetSymbolAddress(&poff, g_off);
    cudaGetSymbolAddress(&plg, g_logits);
    cudaGetSymbolAddress(&pmid, g_mid);
    __half* vh_s = (__half*)pvh;
    __half* wt_s = (__half*)pwt;
    float* off_s = (float*)poff;
    float* lg_s  = (float*)plg;
    float* mid_s = (float*)pmid;

    // 0) transpose + fp16-convert W_v -> Wt[n][k]
    {
        dim3 grid(En / 32, En / 32);
        transpose_w_h<<<grid, dim3(32, 8)>>>(W_v, wt_s);
    }
    // 1) value projection: [156480,256] @ [256,256]  (fp16 MMA, half output)
    {
        dim3 grid(En / 128, (Mv + 127) / 128);
        gemm_f16v<<<grid, 256>>>(value, wt_s, b_v, vh_s, Mv, En, En);
    }
    // 2) sampling-offset projection: [7200,256] @ [256,256]  (tf32)
    {
        dim3 grid(256 / 128, (BQn + 127) / 128);
        gemm_tf32<<<grid, 256>>>(query, W_off, b_off, nullptr, off_s, BQn, 256, En);
    }
    // 3) attention-logit projection: [7200,256] @ [256,128]  (tf32)
    {
        dim3 grid(128 / 128, (BQn + 127) / 128);
        gemm_tf32<<<grid, 256>>>(query, W_attn, b_attn, nullptr, lg_s, BQn, 128, En);
    }
    // 4) softmax + deformable bilinear sampling (fp16 gathers)
    msda_sample<<<BQn, 256>>>(off_s, lg_s, refpts, vh_s, mid_s);
    // 5) output projection + residual: [7200,256] @ [256,256] + query  (tf32)
    {
        dim3 grid(En / 128, (BQn + 127) / 128);
        gemm_tf32<<<grid, 256>>>(mid_s, W_out, b_out, query, out, BQn, En, En);
    }
}